// round 15
// baseline (speedup 1.0000x reference)
#include <cuda_runtime.h>

#define BB 256
#define RR 1152
#define CC 10
#define OO 16
#define II 8
#define CO 160            // CC*OO
#define KK (RR*II)        // 9216
#define NITER 3
#define KSPLIT 72         // k_spart: K chunks of 128 k (16 r)
#define AGREE_CTAS (288*2)

typedef unsigned long long ull;

__device__ float g_b[CC*RR];             // logits [c][r]
__device__ float g_c[CC*RR];             // couplings [c][r]
__device__ float g_part[KSPLIT*BB*CO];   // split-K partials of S (11.8 MB)
__device__ float g_V[BB*CO];             // squashed v [b][co]
__device__ unsigned int g_cnt = 0;       // agree arrival counter (self-resetting)

// ---------------- helpers ---------------------------------------------------
__device__ __forceinline__ ull ffma2(ull a, ull b, ull c) {
    ull d;
    asm("fma.rn.f32x2 %0, %1, %2, %3;" : "=l"(d) : "l"(a), "l"(b), "l"(c));
    return d;
}
__device__ __forceinline__ ull splat2(float x) {
    ull d; unsigned u = __float_as_uint(x);
    asm("mov.b64 %0, {%1, %1};" : "=l"(d) : "r"(u));
    return d;
}
__device__ __forceinline__ void unpack2(ull a, float* lo, float* hi) {
    unsigned l_, h_;
    asm("mov.b64 {%0, %1}, %2;" : "=r"(l_), "=r"(h_) : "l"(a));
    *lo = __uint_as_float(l_); *hi = __uint_as_float(h_);
}
__device__ __forceinline__ float squashf(float s) {
    return s * fabsf(s) / (1.0f + s*s);
}

// ---------------------------------------------------------------------------
// s GEMM partials: part[ks][b][co] = sum_{k in 128-chunk} (cW)[k,co]*x[b,k]
// grid (72, 8), 128 thr, ~4-5 CTAs/SM in ONE wave. Block tile 32b x 160co,
// 16 double-buffered stages of 8 k. Warp w: b rows [w*8, w*8+8), all co.
// Lane l: co {l+32j}. Per k-step: 2 bcast LDS.128 + 5 coalesced LDS.32
// + 5 splat + 20 FFMA2 (all smem ops 1 wavefront).
// ---------------------------------------------------------------------------
__global__ void __launch_bounds__(128, 5) k_spart(const float* __restrict__ x,
                                                  const float* __restrict__ W,
                                                  int uniform) {
    __shared__ __align__(16) float sX[2][8][32];     // [k][b]
    __shared__ __align__(16) float sW[2][8][160];    // [k][co], c-scaled
    __shared__ float sc[160];

    int t = threadIdx.x;
    int w = t >> 5, l = t & 31;
    int ks = blockIdx.x, bt = blockIdx.y;
    int r0 = ks * 16;
    int b0 = bt * 32;
    int wb = w * 8;                   // warp's local b base

    // couplings for the 16 r of this chunk
    if (t < 128)
        sc[t] = uniform ? (1.0f / (float)RR)
                        : g_c[(t % 10)*RR + r0 + (t / 10)];
    if (t < 32)
        sc[t + 128] = uniform ? (1.0f / (float)RR)
                              : g_c[((t + 128) % 10)*RR + r0 + ((t + 128) / 10)];

    // staging roles
    int xb = t >> 1, xh = t & 1;      // t<64: local b, k-half
    float4 rx = make_float4(0,0,0,0);
    float4 rwa, rwb, rwc, rwd;
    float rs1 = 0.0f, rs2 = 0.0f;

    __syncthreads();   // sc ready

    // prologue: load stage 0
    if (t < 64)
        rx = *(const float4*)(x + (size_t)(b0+xb)*KK + r0*8 + xh*4);
    {
        const float* wp = W + ((size_t)r0*CO + t)*II;
        rwa = *(const float4*)wp; rwb = *(const float4*)(wp + 4);
        rs1 = sc[t >> 4];
        if (t < 32) {
            const float* wq = W + ((size_t)r0*CO + t + 128)*II;
            rwc = *(const float4*)wq; rwd = *(const float4*)(wq + 4);
            rs2 = sc[(t + 128) >> 4];
        }
    }
    // commit stage 0
    if (t < 64) {
        sX[0][xh*4+0][xb] = rx.x; sX[0][xh*4+1][xb] = rx.y;
        sX[0][xh*4+2][xb] = rx.z; sX[0][xh*4+3][xb] = rx.w;
    }
    sW[0][0][t] = rwa.x*rs1; sW[0][1][t] = rwa.y*rs1;
    sW[0][2][t] = rwa.z*rs1; sW[0][3][t] = rwa.w*rs1;
    sW[0][4][t] = rwb.x*rs1; sW[0][5][t] = rwb.y*rs1;
    sW[0][6][t] = rwb.z*rs1; sW[0][7][t] = rwb.w*rs1;
    if (t < 32) {
        sW[0][0][t+128] = rwc.x*rs2; sW[0][1][t+128] = rwc.y*rs2;
        sW[0][2][t+128] = rwc.z*rs2; sW[0][3][t+128] = rwc.w*rs2;
        sW[0][4][t+128] = rwd.x*rs2; sW[0][5][t+128] = rwd.y*rs2;
        sW[0][6][t+128] = rwd.z*rs2; sW[0][7][t+128] = rwd.w*rs2;
    }

    ull acc[4][5];
    #pragma unroll
    for (int bp = 0; bp < 4; bp++)
        #pragma unroll
        for (int j = 0; j < 5; j++) acc[bp][j] = 0ull;

    for (int s = 0; s < 16; s++) {
        int p = s & 1;
        if (s < 15) {    // prefetch stage s+1
            int r = r0 + s + 1;
            if (t < 64)
                rx = *(const float4*)(x + (size_t)(b0+xb)*KK + r*8 + xh*4);
            const float* wp = W + ((size_t)r*CO + t)*II;
            rwa = *(const float4*)wp; rwb = *(const float4*)(wp + 4);
            rs1 = sc[(s+1)*10 + (t >> 4)];
            if (t < 32) {
                const float* wq = W + ((size_t)r*CO + t + 128)*II;
                rwc = *(const float4*)wq; rwd = *(const float4*)(wq + 4);
                rs2 = sc[(s+1)*10 + ((t + 128) >> 4)];
            }
        }
        __syncthreads();   // stage s visible

        #pragma unroll
        for (int kk = 0; kk < 8; kk++) {
            const float* xr = &sX[p][kk][wb];
            ulonglong2 xa = *(const ulonglong2*)xr;         // b pairs 0,1
            ulonglong2 xc = *(const ulonglong2*)(xr + 4);   // b pairs 2,3
            ull xp[4] = {xa.x, xa.y, xc.x, xc.y};
            const float* wr = &sW[p][kk][l];
            ull ws[5];
            #pragma unroll
            for (int j = 0; j < 5; j++) ws[j] = splat2(wr[32*j]);
            #pragma unroll
            for (int bp = 0; bp < 4; bp++)
                #pragma unroll
                for (int j = 0; j < 5; j++)
                    acc[bp][j] = ffma2(xp[bp], ws[j], acc[bp][j]);
        }

        if (s < 15) {    // commit prefetched stage into the other buffer
            int q = (s + 1) & 1;
            if (t < 64) {
                sX[q][xh*4+0][xb] = rx.x; sX[q][xh*4+1][xb] = rx.y;
                sX[q][xh*4+2][xb] = rx.z; sX[q][xh*4+3][xb] = rx.w;
            }
            sW[q][0][t] = rwa.x*rs1; sW[q][1][t] = rwa.y*rs1;
            sW[q][2][t] = rwa.z*rs1; sW[q][3][t] = rwa.w*rs1;
            sW[q][4][t] = rwb.x*rs1; sW[q][5][t] = rwb.y*rs1;
            sW[q][6][t] = rwb.z*rs1; sW[q][7][t] = rwb.w*rs1;
            if (t < 32) {
                sW[q][0][t+128] = rwc.x*rs2; sW[q][1][t+128] = rwc.y*rs2;
                sW[q][2][t+128] = rwc.z*rs2; sW[q][3][t+128] = rwc.w*rs2;
                sW[q][4][t+128] = rwd.x*rs2; sW[q][5][t+128] = rwd.y*rs2;
                sW[q][6][t+128] = rwd.z*rs2; sW[q][7][t+128] = rwd.w*rs2;
            }
        }
    }

    // epilogue: coalesced scalar stores (lanes = consecutive co)
    float* dst = g_part + (size_t)ks*BB*CO + (size_t)b0*CO;
    #pragma unroll
    for (int bp = 0; bp < 4; bp++) {
        float lo[5], hi[5];
        #pragma unroll
        for (int j = 0; j < 5; j++) unpack2(acc[bp][j], &lo[j], &hi[j]);
        float* ra = dst + (size_t)(wb + 2*bp)*CO + l;
        float* rb = ra + CO;
        #pragma unroll
        for (int j = 0; j < 5; j++) { ra[32*j] = lo[j]; rb[32*j] = hi[j]; }
    }
}

// ---------------------------------------------------------------------------
// reduce split-K partials, squash -> g_V (+ final output); optionally zero g_b
// grid 160 x 256: 64 f4 per block, 4-way p-split (18 each) + smem tree
// ---------------------------------------------------------------------------
__global__ void __launch_bounds__(256) k_sqreduce(float* __restrict__ out,
                                                  int write_out, int zero_b) {
    __shared__ float4 red[256];
    int t = threadIdx.x;
    if (zero_b) {
        int gid = blockIdx.x * 256 + t;
        if (gid < CC*RR) g_b[gid] = 0.0f;
    }
    int i4 = t & 63, pg = t >> 6;
    int idx4 = blockIdx.x * 64 + i4;
    float4 s = make_float4(0,0,0,0);
    #pragma unroll 6
    for (int p = pg*18; p < (pg+1)*18; p++) {
        float4 v = *(const float4*)(g_part + (size_t)p*BB*CO + (size_t)idx4*4);
        s.x += v.x; s.y += v.y; s.z += v.z; s.w += v.w;
    }
    red[t] = s;
    __syncthreads();
    if (t < 64) {
        float4 a = red[t], b = red[t+64], c = red[t+128], d = red[t+192];
        s.x = (a.x + b.x) + (c.x + d.x);
        s.y = (a.y + b.y) + (c.y + d.y);
        s.z = (a.z + b.z) + (c.z + d.z);
        s.w = (a.w + b.w) + (c.w + d.w);
        float4 q;
        q.x = squashf(s.x); q.y = squashf(s.y);
        q.z = squashf(s.z); q.w = squashf(s.w);
        *(float4*)(g_V + (size_t)idx4*4) = q;
        if (write_out) *(float4*)(out + (size_t)idx4*4) = q;
    }
}

// ---------------------------------------------------------------------------
// agree: partial G[k,co] = sum_{b half} x[b,k]*V[b,co]; contract with W,
// atomicAdd logits. grid (288, 2), 128 thr, 4 routes (32 k) per CTA.
// FUSED TAIL: the last-arriving CTA (fence + counter) computes the softmax
// over routes for all 10 classes and resets the counter.
// ---------------------------------------------------------------------------
__global__ void __launch_bounds__(128, 5) k_agree(const float* __restrict__ x,
                                                  const float* __restrict__ W) {
    __shared__ __align__(16) float sm[6272];   // reused as sG [32][162]
    float* sV  = sm;          // [32][160] = 5120
    float* sXa = sm + 5120;   // [32][32]  = 1024
    __shared__ float sred[4];
    __shared__ unsigned int sIsLast;

    int t = threadIdx.x;
    int w = t >> 5, l = t & 31;
    int r0 = blockIdx.x * 4;       // 4 routes
    int k0 = r0 * 8;               // 32 k
    int wk = w * 8;                // warp's local k base

    ull acc[4][5];                 // 4 k-pairs x 5 strided co
    #pragma unroll
    for (int kp = 0; kp < 4; kp++)
        #pragma unroll
        for (int j = 0; j < 5; j++) acc[kp][j] = 0ull;

    for (int sub = 0; sub < 4; sub++) {
        int bs0 = blockIdx.y * 128 + sub * 32;
        __syncthreads();
        // stage V: 1280 f4 coalesced (10 per thread)
        #pragma unroll
        for (int q = 0; q < 10; q++) {
            int idx = t + q*128;
            *(float4*)&sV[idx*4] =
                *(const float4*)(g_V + (size_t)bs0*CO + (size_t)idx*4);
        }
        // stage x: direct copy, k-contiguous (256 f4)
        #pragma unroll
        for (int q = 0; q < 2; q++) {
            int idx = t + q*128;           // 0..255
            int bb = idx >> 3, kq = idx & 7;
            *(float4*)&sXa[bb*32 + kq*4] =
                *(const float4*)(x + (size_t)(bs0+bb)*KK + k0 + kq*4);
        }
        __syncthreads();

        #pragma unroll 2
        for (int b = 0; b < 32; b++) {
            const float* xr = &sXa[b*32 + wk];
            ulonglong2 xa = *(const ulonglong2*)xr;        // k pairs 0,1
            ulonglong2 xc = *(const ulonglong2*)(xr + 4);  // k pairs 2,3
            ull xp[4] = {xa.x, xa.y, xc.x, xc.y};
            const float* vr = &sV[b*160 + l];
            ull vs[5];
            #pragma unroll
            for (int j = 0; j < 5; j++) vs[j] = splat2(vr[32*j]);
            #pragma unroll
            for (int kp = 0; kp < 4; kp++)
                #pragma unroll
                for (int j = 0; j < 5; j++)
                    acc[kp][j] = ffma2(xp[kp], vs[j], acc[kp][j]);
        }
    }
    __syncthreads();

    // spill partial G: sG[k][co], stride 162, coalesced scalar stores
    #pragma unroll
    for (int kp = 0; kp < 4; kp++) {
        float lo[5], hi[5];
        #pragma unroll
        for (int j = 0; j < 5; j++) unpack2(acc[kp][j], &lo[j], &hi[j]);
        float* ra = &sm[(wk + 2*kp)*162 + l];
        float* rb = ra + 162;
        #pragma unroll
        for (int j = 0; j < 5; j++) { ra[32*j] = lo[j]; rb[32*j] = hi[j]; }
    }
    __syncthreads();

    // contraction: warp w -> route r0+w
    int r = r0 + w;
    const float* G = &sm[(w*8)*162];
    for (int c = 0; c < CC; c++) {
        float4 w4 = *(const float4*)(W + ((size_t)r*CC + c)*OO*II + 4*l);
        int e0 = 4*l;
        float p = w4.x * G[((e0  )&7)*162 + c*16 + ((e0  )>>3)]
                + w4.y * G[((e0+1)&7)*162 + c*16 + ((e0+1)>>3)]
                + w4.z * G[((e0+2)&7)*162 + c*16 + ((e0+2)>>3)]
                + w4.w * G[((e0+3)&7)*162 + c*16 + ((e0+3)>>3)];
        #pragma unroll
        for (int off = 16; off; off >>= 1)
            p += __shfl_xor_sync(0xffffffffu, p, off);
        if (l == 0) atomicAdd(&g_b[c*RR + r], p * (1.0f / (float)BB));
    }

    // ---- fused softmax: fence + arrival counter; last CTA does all classes
    __threadfence();
    __syncthreads();
    if (t == 0) {
        unsigned v = atomicAdd(&g_cnt, 1u);
        sIsLast = (v == AGREE_CTAS - 1) ? 1u : 0u;
    }
    __syncthreads();
    if (sIsLast) {
        __threadfence();   // acquire: all logit atomics visible
        for (int c = 0; c < CC; c++) {
            float m = -1e30f;
            for (int rr = t; rr < RR; rr += 128)
                m = fmaxf(m, __ldcg(&g_b[c*RR + rr]));
            #pragma unroll
            for (int off = 16; off; off >>= 1)
                m = fmaxf(m, __shfl_xor_sync(~0u, m, off));
            if (l == 0) sred[w] = m;
            __syncthreads();
            m = fmaxf(fmaxf(sred[0], sred[1]), fmaxf(sred[2], sred[3]));
            __syncthreads();

            float sum = 0.0f;
            for (int rr = t; rr < RR; rr += 128)
                sum += __expf(__ldcg(&g_b[c*RR + rr]) - m);
            #pragma unroll
            for (int off = 16; off; off >>= 1)
                sum += __shfl_xor_sync(~0u, sum, off);
            if (l == 0) sred[w] = sum;
            __syncthreads();
            float inv = 1.0f / (((sred[0] + sred[1]) + (sred[2] + sred[3])));
            __syncthreads();

            for (int rr = t; rr < RR; rr += 128)
                g_c[c*RR + rr] = __expf(__ldcg(&g_b[c*RR + rr]) - m) * inv;
        }
        __threadfence();
        if (t == 0) g_cnt = 0;   // reset for next call
    }
}

// ---------------------------------------------------------------------------
extern "C" void kernel_launch(void* const* d_in, const int* in_sizes, int n_in,
                              void* d_out, int out_size) {
    const float* x = (const float*)d_in[0];
    const float* W = (const float*)d_in[1];
    if (in_sizes[0] == RR*CC*OO*II && in_sizes[1] == BB*RR*II) {
        W = (const float*)d_in[0];
        x = (const float*)d_in[1];
    }
    float* out = (float*)d_out;

    for (int it = 0; it < NITER; it++) {
        k_spart<<<dim3(KSPLIT, 8), 128>>>(x, W, it == 0 ? 1 : 0);
        k_sqreduce<<<160, 256>>>(out, it == NITER - 1 ? 1 : 0,
                                 it == 0 ? 1 : 0);
        if (it < NITER - 1) {
            k_agree<<<dim3(288, 2), 128>>>(x, W);
        }
    }
}

// round 16
// speedup vs baseline: 2.2962x; 2.2962x over previous
#include <cuda_runtime.h>

#define BB 256
#define RR 1152
#define CC 10
#define OO 16
#define II 8
#define CO 160            // CC*OO
#define KK (RR*II)        // 9216
#define NITER 3
#define KSPLIT 72         // k_spart: K chunks of 128 k (16 r)

typedef unsigned long long ull;

__device__ float g_b[CC*RR];             // logits [c][r]
__device__ float g_c[CC*RR];             // couplings [c][r]
__device__ float g_part[KSPLIT*BB*CO];   // split-K partials of S (11.8 MB)
__device__ float g_V[BB*CO];             // squashed v [b][co]

// ---------------- helpers ---------------------------------------------------
__device__ __forceinline__ ull ffma2(ull a, ull b, ull c) {
    ull d;
    asm("fma.rn.f32x2 %0, %1, %2, %3;" : "=l"(d) : "l"(a), "l"(b), "l"(c));
    return d;
}
__device__ __forceinline__ ull splat2(float x) {
    ull d; unsigned u = __float_as_uint(x);
    asm("mov.b64 %0, {%1, %1};" : "=l"(d) : "r"(u));
    return d;
}
__device__ __forceinline__ void unpack2(ull a, float* lo, float* hi) {
    unsigned l_, h_;
    asm("mov.b64 {%0, %1}, %2;" : "=r"(l_), "=r"(h_) : "l"(a));
    *lo = __uint_as_float(l_); *hi = __uint_as_float(h_);
}
__device__ __forceinline__ float squashf(float s) {
    return s * fabsf(s) / (1.0f + s*s);
}

// ---------------------------------------------------------------------------
// s GEMM partials: part[ks][b][co] = sum_{k in 128-chunk} (cW)[k,co]*x[b,k]
// grid (72, 8), 128 thr, ~4-5 CTAs/SM in ONE wave. Block tile 32b x 160co,
// 16 double-buffered stages of 8 k. Warp w: b rows [w*8, w*8+8), all co.
// Lane l: co {l+32j}. Per k-step: 2 bcast LDS.128 + 5 coalesced LDS.32
// + 5 splat + 20 FFMA2 (all smem ops 1 wavefront).
// ---------------------------------------------------------------------------
__global__ void __launch_bounds__(128, 5) k_spart(const float* __restrict__ x,
                                                  const float* __restrict__ W,
                                                  int uniform) {
    __shared__ __align__(16) float sX[2][8][32];     // [k][b]
    __shared__ __align__(16) float sW[2][8][160];    // [k][co], c-scaled
    __shared__ float sc[160];

    int t = threadIdx.x;
    int w = t >> 5, l = t & 31;
    int ks = blockIdx.x, bt = blockIdx.y;
    int r0 = ks * 16;
    int b0 = bt * 32;
    int wb = w * 8;                   // warp's local b base

    // couplings for the 16 r of this chunk
    if (t < 128)
        sc[t] = uniform ? (1.0f / (float)RR)
                        : g_c[(t % 10)*RR + r0 + (t / 10)];
    if (t < 32)
        sc[t + 128] = uniform ? (1.0f / (float)RR)
                              : g_c[((t + 128) % 10)*RR + r0 + ((t + 128) / 10)];

    // staging roles
    int xb = t >> 1, xh = t & 1;      // t<64: local b, k-half
    float4 rx = make_float4(0,0,0,0);
    float4 rwa, rwb, rwc, rwd;
    float rs1 = 0.0f, rs2 = 0.0f;

    __syncthreads();   // sc ready

    // prologue: load stage 0
    if (t < 64)
        rx = *(const float4*)(x + (size_t)(b0+xb)*KK + r0*8 + xh*4);
    {
        const float* wp = W + ((size_t)r0*CO + t)*II;
        rwa = *(const float4*)wp; rwb = *(const float4*)(wp + 4);
        rs1 = sc[t >> 4];
        if (t < 32) {
            const float* wq = W + ((size_t)r0*CO + t + 128)*II;
            rwc = *(const float4*)wq; rwd = *(const float4*)(wq + 4);
            rs2 = sc[(t + 128) >> 4];
        }
    }
    // commit stage 0
    if (t < 64) {
        sX[0][xh*4+0][xb] = rx.x; sX[0][xh*4+1][xb] = rx.y;
        sX[0][xh*4+2][xb] = rx.z; sX[0][xh*4+3][xb] = rx.w;
    }
    sW[0][0][t] = rwa.x*rs1; sW[0][1][t] = rwa.y*rs1;
    sW[0][2][t] = rwa.z*rs1; sW[0][3][t] = rwa.w*rs1;
    sW[0][4][t] = rwb.x*rs1; sW[0][5][t] = rwb.y*rs1;
    sW[0][6][t] = rwb.z*rs1; sW[0][7][t] = rwb.w*rs1;
    if (t < 32) {
        sW[0][0][t+128] = rwc.x*rs2; sW[0][1][t+128] = rwc.y*rs2;
        sW[0][2][t+128] = rwc.z*rs2; sW[0][3][t+128] = rwc.w*rs2;
        sW[0][4][t+128] = rwd.x*rs2; sW[0][5][t+128] = rwd.y*rs2;
        sW[0][6][t+128] = rwd.z*rs2; sW[0][7][t+128] = rwd.w*rs2;
    }

    ull acc[4][5];
    #pragma unroll
    for (int bp = 0; bp < 4; bp++)
        #pragma unroll
        for (int j = 0; j < 5; j++) acc[bp][j] = 0ull;

    for (int s = 0; s < 16; s++) {
        int p = s & 1;
        if (s < 15) {    // prefetch stage s+1
            int r = r0 + s + 1;
            if (t < 64)
                rx = *(const float4*)(x + (size_t)(b0+xb)*KK + r*8 + xh*4);
            const float* wp = W + ((size_t)r*CO + t)*II;
            rwa = *(const float4*)wp; rwb = *(const float4*)(wp + 4);
            rs1 = sc[(s+1)*10 + (t >> 4)];
            if (t < 32) {
                const float* wq = W + ((size_t)r*CO + t + 128)*II;
                rwc = *(const float4*)wq; rwd = *(const float4*)(wq + 4);
                rs2 = sc[(s+1)*10 + ((t + 128) >> 4)];
            }
        }
        __syncthreads();   // stage s visible

        #pragma unroll
        for (int kk = 0; kk < 8; kk++) {
            const float* xr = &sX[p][kk][wb];
            ulonglong2 xa = *(const ulonglong2*)xr;         // b pairs 0,1
            ulonglong2 xc = *(const ulonglong2*)(xr + 4);   // b pairs 2,3
            ull xp[4] = {xa.x, xa.y, xc.x, xc.y};
            const float* wr = &sW[p][kk][l];
            ull ws[5];
            #pragma unroll
            for (int j = 0; j < 5; j++) ws[j] = splat2(wr[32*j]);
            #pragma unroll
            for (int bp = 0; bp < 4; bp++)
                #pragma unroll
                for (int j = 0; j < 5; j++)
                    acc[bp][j] = ffma2(xp[bp], ws[j], acc[bp][j]);
        }

        if (s < 15) {    // commit prefetched stage into the other buffer
            int q = (s + 1) & 1;
            if (t < 64) {
                sX[q][xh*4+0][xb] = rx.x; sX[q][xh*4+1][xb] = rx.y;
                sX[q][xh*4+2][xb] = rx.z; sX[q][xh*4+3][xb] = rx.w;
            }
            sW[q][0][t] = rwa.x*rs1; sW[q][1][t] = rwa.y*rs1;
            sW[q][2][t] = rwa.z*rs1; sW[q][3][t] = rwa.w*rs1;
            sW[q][4][t] = rwb.x*rs1; sW[q][5][t] = rwb.y*rs1;
            sW[q][6][t] = rwb.z*rs1; sW[q][7][t] = rwb.w*rs1;
            if (t < 32) {
                sW[q][0][t+128] = rwc.x*rs2; sW[q][1][t+128] = rwc.y*rs2;
                sW[q][2][t+128] = rwc.z*rs2; sW[q][3][t+128] = rwc.w*rs2;
                sW[q][4][t+128] = rwd.x*rs2; sW[q][5][t+128] = rwd.y*rs2;
                sW[q][6][t+128] = rwd.z*rs2; sW[q][7][t+128] = rwd.w*rs2;
            }
        }
    }

    // epilogue: coalesced scalar stores (lanes = consecutive co)
    float* dst = g_part + (size_t)ks*BB*CO + (size_t)b0*CO;
    #pragma unroll
    for (int bp = 0; bp < 4; bp++) {
        float lo[5], hi[5];
        #pragma unroll
        for (int j = 0; j < 5; j++) unpack2(acc[bp][j], &lo[j], &hi[j]);
        float* ra = dst + (size_t)(wb + 2*bp)*CO + l;
        float* rb = ra + CO;
        #pragma unroll
        for (int j = 0; j < 5; j++) { ra[32*j] = lo[j]; rb[32*j] = hi[j]; }
    }
}

// ---------------------------------------------------------------------------
// reduce split-K partials, squash -> g_V (+ final output); optionally zero g_b
// grid 160 x 256: 64 f4 per block, 4-way p-split (18 each) + smem tree
// ---------------------------------------------------------------------------
__global__ void __launch_bounds__(256) k_sqreduce(float* __restrict__ out,
                                                  int write_out, int zero_b) {
    __shared__ float4 red[256];
    int t = threadIdx.x;
    if (zero_b) {
        int gid = blockIdx.x * 256 + t;
        if (gid < CC*RR) g_b[gid] = 0.0f;
    }
    int i4 = t & 63, pg = t >> 6;
    int idx4 = blockIdx.x * 64 + i4;
    float4 s = make_float4(0,0,0,0);
    #pragma unroll 6
    for (int p = pg*18; p < (pg+1)*18; p++) {
        float4 v = *(const float4*)(g_part + (size_t)p*BB*CO + (size_t)idx4*4);
        s.x += v.x; s.y += v.y; s.z += v.z; s.w += v.w;
    }
    red[t] = s;
    __syncthreads();
    if (t < 64) {
        float4 a = red[t], b = red[t+64], c = red[t+128], d = red[t+192];
        s.x = (a.x + b.x) + (c.x + d.x);
        s.y = (a.y + b.y) + (c.y + d.y);
        s.z = (a.z + b.z) + (c.z + d.z);
        s.w = (a.w + b.w) + (c.w + d.w);
        float4 q;
        q.x = squashf(s.x); q.y = squashf(s.y);
        q.z = squashf(s.z); q.w = squashf(s.w);
        *(float4*)(g_V + (size_t)idx4*4) = q;
        if (write_out) *(float4*)(out + (size_t)idx4*4) = q;
    }
}

// ---------------------------------------------------------------------------
// agree: partial G[k,co] = sum_{b half} x[b,k]*V[b,co]; contract with W,
// atomicAdd logits. grid (288, 2), 128 thr, 4 routes (32 k) per CTA.
// x block (128 b x 32 k = 16 KB) staged ONCE upfront; only V staged per sub.
// ---------------------------------------------------------------------------
__global__ void __launch_bounds__(128, 5) k_agree(const float* __restrict__ x,
                                                  const float* __restrict__ W) {
    __shared__ __align__(16) float sV[5184];    // [32][160]; reused as sG [32][162]
    __shared__ __align__(16) float sXa[4096];   // [128][32], k-contiguous

    int t = threadIdx.x;
    int w = t >> 5, l = t & 31;
    int r0 = blockIdx.x * 4;       // 4 routes
    int k0 = r0 * 8;               // 32 k
    int wk = w * 8;                // warp's local k base

    // stage ALL x upfront: 128 b x 32 k = 1024 f4 (8 per thread)
    {
        int bbase = blockIdx.y * 128;
        #pragma unroll
        for (int q = 0; q < 8; q++) {
            int idx = t + q*128;           // 0..1023
            int bb = idx >> 3, kq = idx & 7;
            *(float4*)&sXa[bb*32 + kq*4] =
                *(const float4*)(x + (size_t)(bbase+bb)*KK + k0 + kq*4);
        }
    }

    ull acc[4][5];                 // 4 k-pairs x 5 strided co
    #pragma unroll
    for (int kp = 0; kp < 4; kp++)
        #pragma unroll
        for (int j = 0; j < 5; j++) acc[kp][j] = 0ull;

    for (int sub = 0; sub < 4; sub++) {
        int bs0 = blockIdx.y * 128 + sub * 32;
        __syncthreads();
        // stage V: 1280 f4 coalesced (10 per thread)
        #pragma unroll
        for (int q = 0; q < 10; q++) {
            int idx = t + q*128;
            *(float4*)&sV[idx*4] =
                *(const float4*)(g_V + (size_t)bs0*CO + (size_t)idx*4);
        }
        __syncthreads();

        const float* xbase = &sXa[(sub*32)*32];
        #pragma unroll 2
        for (int b = 0; b < 32; b++) {
            const float* xr = xbase + b*32 + wk;
            ulonglong2 xa = *(const ulonglong2*)xr;        // k pairs 0,1
            ulonglong2 xc = *(const ulonglong2*)(xr + 4);  // k pairs 2,3
            ull xp[4] = {xa.x, xa.y, xc.x, xc.y};
            const float* vr = &sV[b*160 + l];
            ull vs[5];
            #pragma unroll
            for (int j = 0; j < 5; j++) vs[j] = splat2(vr[32*j]);
            #pragma unroll
            for (int kp = 0; kp < 4; kp++)
                #pragma unroll
                for (int j = 0; j < 5; j++)
                    acc[kp][j] = ffma2(xp[kp], vs[j], acc[kp][j]);
        }
    }
    __syncthreads();

    // spill partial G into sV region: sG[k][co], stride 162
    #pragma unroll
    for (int kp = 0; kp < 4; kp++) {
        float lo[5], hi[5];
        #pragma unroll
        for (int j = 0; j < 5; j++) unpack2(acc[kp][j], &lo[j], &hi[j]);
        float* ra = &sV[(wk + 2*kp)*162 + l];
        float* rb = ra + 162;
        #pragma unroll
        for (int j = 0; j < 5; j++) { ra[32*j] = lo[j]; rb[32*j] = hi[j]; }
    }
    __syncthreads();

    // contraction: warp w -> route r0+w
    int r = r0 + w;
    const float* G = &sV[(w*8)*162];
    for (int c = 0; c < CC; c++) {
        float4 w4 = *(const float4*)(W + ((size_t)r*CC + c)*OO*II + 4*l);
        int e0 = 4*l;
        float p = w4.x * G[((e0  )&7)*162 + c*16 + ((e0  )>>3)]
                + w4.y * G[((e0+1)&7)*162 + c*16 + ((e0+1)>>3)]
                + w4.z * G[((e0+2)&7)*162 + c*16 + ((e0+2)>>3)]
                + w4.w * G[((e0+3)&7)*162 + c*16 + ((e0+3)>>3)];
        #pragma unroll
        for (int off = 16; off; off >>= 1)
            p += __shfl_xor_sync(0xffffffffu, p, off);
        if (l == 0) atomicAdd(&g_b[c*RR + r], p * (1.0f / (float)BB));
    }
}

// ---------------------------------------------------------------------------
// softmax over routes per class ([c][r] layout)
// ---------------------------------------------------------------------------
__global__ void __launch_bounds__(256) k_softmax() {
    int c = blockIdx.x, t = threadIdx.x;
    __shared__ float red[8];

    float v[5];
    #pragma unroll
    for (int q = 0; q < 5; q++) {
        int r = t + q*256;
        v[q] = (r < RR) ? g_b[c*RR + r] : -1e30f;
    }
    float m = fmaxf(fmaxf(fmaxf(v[0], v[1]), fmaxf(v[2], v[3])), v[4]);
    #pragma unroll
    for (int off = 16; off; off >>= 1) m = fmaxf(m, __shfl_xor_sync(~0u, m, off));
    if ((t & 31) == 0) red[t >> 5] = m;
    __syncthreads();
    m = red[0];
    #pragma unroll
    for (int q = 1; q < 8; q++) m = fmaxf(m, red[q]);

    float e[5], sum = 0.0f;
    #pragma unroll
    for (int q = 0; q < 5; q++) {
        int r = t + q*256;
        e[q] = (r < RR) ? __expf(v[q] - m) : 0.0f;
        sum += e[q];
    }
    #pragma unroll
    for (int off = 16; off; off >>= 1) sum += __shfl_xor_sync(~0u, sum, off);
    __syncthreads();
    if ((t & 31) == 0) red[t >> 5] = sum;
    __syncthreads();
    sum = 0.0f;
    #pragma unroll
    for (int q = 0; q < 8; q++) sum += red[q];
    float inv = 1.0f / sum;

    #pragma unroll
    for (int q = 0; q < 5; q++) {
        int r = t + q*256;
        if (r < RR) g_c[c*RR + r] = e[q] * inv;
    }
}

// ---------------------------------------------------------------------------
extern "C" void kernel_launch(void* const* d_in, const int* in_sizes, int n_in,
                              void* d_out, int out_size) {
    const float* x = (const float*)d_in[0];
    const float* W = (const float*)d_in[1];
    if (in_sizes[0] == RR*CC*OO*II && in_sizes[1] == BB*RR*II) {
        W = (const float*)d_in[0];
        x = (const float*)d_in[1];
    }
    float* out = (float*)d_out;

    for (int it = 0; it < NITER; it++) {
        k_spart<<<dim3(KSPLIT, 8), 128>>>(x, W, it == 0 ? 1 : 0);
        k_sqreduce<<<160, 256>>>(out, it == NITER - 1 ? 1 : 0,
                                 it == 0 ? 1 : 0);
        if (it < NITER - 1) {
            k_agree<<<dim3(288, 2), 128>>>(x, W);
            k_softmax<<<CC, 256>>>();
        }
    }
}

// round 17
// speedup vs baseline: 2.3692x; 1.0318x over previous
#include <cuda_runtime.h>

#define BB 256
#define RR 1152
#define CC 10
#define OO 16
#define II 8
#define CO 160            // CC*OO
#define KK (RR*II)        // 9216
#define NITER 3
#define KSPLIT 72         // k_spart: K chunks of 128 k (16 r)

typedef unsigned long long ull;

__device__ float g_b[CC*RR];             // logits [c][r]
__device__ float g_c[CC*RR];             // couplings [c][r]
__device__ float g_part[KSPLIT*BB*CO];   // split-K partials of S (11.8 MB)
__device__ float g_V[BB*CO];             // squashed v [b][co]

// ---------------- helpers ---------------------------------------------------
__device__ __forceinline__ ull ffma2(ull a, ull b, ull c) {
    ull d;
    asm("fma.rn.f32x2 %0, %1, %2, %3;" : "=l"(d) : "l"(a), "l"(b), "l"(c));
    return d;
}
__device__ __forceinline__ ull splat2(float x) {
    ull d; unsigned u = __float_as_uint(x);
    asm("mov.b64 %0, {%1, %1};" : "=l"(d) : "r"(u));
    return d;
}
__device__ __forceinline__ void unpack2(ull a, float* lo, float* hi) {
    unsigned l_, h_;
    asm("mov.b64 {%0, %1}, %2;" : "=r"(l_), "=r"(h_) : "l"(a));
    *lo = __uint_as_float(l_); *hi = __uint_as_float(h_);
}
__device__ __forceinline__ float squashf(float s) {
    return s * fabsf(s) / (1.0f + s*s);
}

// ---------------------------------------------------------------------------
// s GEMM partials: part[ks][b][co] = sum_{k in 128-chunk} (cW)[k,co]*x[b,k]
// grid (72, 4), 256 thr (8 warps), ~2 CTAs/SM in ONE wave.
// Block tile 64b x 160co, 16 double-buffered stages of 8 k.
// Warp w: b rows [w*8, w*8+8), all co. Lane l: co {l+32j}.
// Per k-step per warp: 2 bcast LDS.128 + 5 coalesced LDS.32 + 5 splat
// + 20 FFMA2. W staging amortized over 2x outputs vs the 128-thr version.
// ---------------------------------------------------------------------------
__global__ void __launch_bounds__(256, 2) k_spart(const float* __restrict__ x,
                                                  const float* __restrict__ W,
                                                  int uniform) {
    __shared__ __align__(16) float sX[2][8][64];     // [k][b]
    __shared__ __align__(16) float sW[2][8][160];    // [k][co], c-scaled
    __shared__ float sc[160];

    int t = threadIdx.x;
    int w = t >> 5, l = t & 31;
    int ks = blockIdx.x, bt = blockIdx.y;
    int r0 = ks * 16;
    int b0 = bt * 64;
    int wb = w * 8;                   // warp's local b base

    // couplings for the 16 r of this chunk (160 values)
    if (t < 160)
        sc[t] = uniform ? (1.0f / (float)RR)
                        : g_c[(t % 10)*RR + r0 + (t / 10)];

    // staging roles
    int xb = t >> 1, xh = t & 1;      // t<128: local b (0..63), k-half
    float4 rx = make_float4(0,0,0,0);
    float4 rwa, rwb;
    float rs1 = 0.0f;

    __syncthreads();   // sc ready

    // prologue: load stage 0
    if (t < 128)
        rx = *(const float4*)(x + (size_t)(b0+xb)*KK + r0*8 + xh*4);
    if (t < 160) {
        const float* wp = W + ((size_t)r0*CO + t)*II;
        rwa = *(const float4*)wp; rwb = *(const float4*)(wp + 4);
        rs1 = sc[t >> 4];
    }
    // commit stage 0
    if (t < 128) {
        sX[0][xh*4+0][xb] = rx.x; sX[0][xh*4+1][xb] = rx.y;
        sX[0][xh*4+2][xb] = rx.z; sX[0][xh*4+3][xb] = rx.w;
    }
    if (t < 160) {
        sW[0][0][t] = rwa.x*rs1; sW[0][1][t] = rwa.y*rs1;
        sW[0][2][t] = rwa.z*rs1; sW[0][3][t] = rwa.w*rs1;
        sW[0][4][t] = rwb.x*rs1; sW[0][5][t] = rwb.y*rs1;
        sW[0][6][t] = rwb.z*rs1; sW[0][7][t] = rwb.w*rs1;
    }

    ull acc[4][5];
    #pragma unroll
    for (int bp = 0; bp < 4; bp++)
        #pragma unroll
        for (int j = 0; j < 5; j++) acc[bp][j] = 0ull;

    for (int s = 0; s < 16; s++) {
        int p = s & 1;
        if (s < 15) {    // prefetch stage s+1
            int r = r0 + s + 1;
            if (t < 128)
                rx = *(const float4*)(x + (size_t)(b0+xb)*KK + r*8 + xh*4);
            if (t < 160) {
                const float* wp = W + ((size_t)r*CO + t)*II;
                rwa = *(const float4*)wp; rwb = *(const float4*)(wp + 4);
                rs1 = sc[(s+1)*10 + (t >> 4)];
            }
        }
        __syncthreads();   // stage s visible

        #pragma unroll
        for (int kk = 0; kk < 8; kk++) {
            const float* xr = &sX[p][kk][wb];
            ulonglong2 xa = *(const ulonglong2*)xr;         // b pairs 0,1
            ulonglong2 xc = *(const ulonglong2*)(xr + 4);   // b pairs 2,3
            ull xp[4] = {xa.x, xa.y, xc.x, xc.y};
            const float* wr = &sW[p][kk][l];
            ull ws[5];
            #pragma unroll
            for (int j = 0; j < 5; j++) ws[j] = splat2(wr[32*j]);
            #pragma unroll
            for (int bp = 0; bp < 4; bp++)
                #pragma unroll
                for (int j = 0; j < 5; j++)
                    acc[bp][j] = ffma2(xp[bp], ws[j], acc[bp][j]);
        }

        if (s < 15) {    // commit prefetched stage into the other buffer
            int q = (s + 1) & 1;
            if (t < 128) {
                sX[q][xh*4+0][xb] = rx.x; sX[q][xh*4+1][xb] = rx.y;
                sX[q][xh*4+2][xb] = rx.z; sX[q][xh*4+3][xb] = rx.w;
            }
            if (t < 160) {
                sW[q][0][t] = rwa.x*rs1; sW[q][1][t] = rwa.y*rs1;
                sW[q][2][t] = rwa.z*rs1; sW[q][3][t] = rwa.w*rs1;
                sW[q][4][t] = rwb.x*rs1; sW[q][5][t] = rwb.y*rs1;
                sW[q][6][t] = rwb.z*rs1; sW[q][7][t] = rwb.w*rs1;
            }
        }
    }

    // epilogue: coalesced scalar stores (lanes = consecutive co)
    float* dst = g_part + (size_t)ks*BB*CO + (size_t)b0*CO;
    #pragma unroll
    for (int bp = 0; bp < 4; bp++) {
        float lo[5], hi[5];
        #pragma unroll
        for (int j = 0; j < 5; j++) unpack2(acc[bp][j], &lo[j], &hi[j]);
        float* ra = dst + (size_t)(wb + 2*bp)*CO + l;
        float* rb = ra + CO;
        #pragma unroll
        for (int j = 0; j < 5; j++) { ra[32*j] = lo[j]; rb[32*j] = hi[j]; }
    }
}

// ---------------------------------------------------------------------------
// reduce split-K partials, squash -> g_V (+ final output); optionally zero g_b
// grid 160 x 256: 64 f4 per block, 4-way p-split (18 each) + smem tree
// ---------------------------------------------------------------------------
__global__ void __launch_bounds__(256) k_sqreduce(float* __restrict__ out,
                                                  int write_out, int zero_b) {
    __shared__ float4 red[256];
    int t = threadIdx.x;
    if (zero_b) {
        int gid = blockIdx.x * 256 + t;
        if (gid < CC*RR) g_b[gid] = 0.0f;
    }
    int i4 = t & 63, pg = t >> 6;
    int idx4 = blockIdx.x * 64 + i4;
    float4 s = make_float4(0,0,0,0);
    #pragma unroll 6
    for (int p = pg*18; p < (pg+1)*18; p++) {
        float4 v = *(const float4*)(g_part + (size_t)p*BB*CO + (size_t)idx4*4);
        s.x += v.x; s.y += v.y; s.z += v.z; s.w += v.w;
    }
    red[t] = s;
    __syncthreads();
    if (t < 64) {
        float4 a = red[t], b = red[t+64], c = red[t+128], d = red[t+192];
        s.x = (a.x + b.x) + (c.x + d.x);
        s.y = (a.y + b.y) + (c.y + d.y);
        s.z = (a.z + b.z) + (c.z + d.z);
        s.w = (a.w + b.w) + (c.w + d.w);
        float4 q;
        q.x = squashf(s.x); q.y = squashf(s.y);
        q.z = squashf(s.z); q.w = squashf(s.w);
        *(float4*)(g_V + (size_t)idx4*4) = q;
        if (write_out) *(float4*)(out + (size_t)idx4*4) = q;
    }
}

// ---------------------------------------------------------------------------
// agree: partial G[k,co] = sum_{b half} x[b,k]*V[b,co]; contract with W,
// atomicAdd logits. grid (288, 2), 128 thr, 4 routes (32 k) per CTA.
// x block (128 b x 32 k = 16 KB) staged ONCE upfront; only V staged per sub.
// ---------------------------------------------------------------------------
__global__ void __launch_bounds__(128, 5) k_agree(const float* __restrict__ x,
                                                  const float* __restrict__ W) {
    __shared__ __align__(16) float sV[5184];    // [32][160]; reused as sG [32][162]
    __shared__ __align__(16) float sXa[4096];   // [128][32], k-contiguous

    int t = threadIdx.x;
    int w = t >> 5, l = t & 31;
    int r0 = blockIdx.x * 4;       // 4 routes
    int k0 = r0 * 8;               // 32 k
    int wk = w * 8;                // warp's local k base

    // stage ALL x upfront: 128 b x 32 k = 1024 f4 (8 per thread)
    {
        int bbase = blockIdx.y * 128;
        #pragma unroll
        for (int q = 0; q < 8; q++) {
            int idx = t + q*128;           // 0..1023
            int bb = idx >> 3, kq = idx & 7;
            *(float4*)&sXa[bb*32 + kq*4] =
                *(const float4*)(x + (size_t)(bbase+bb)*KK + k0 + kq*4);
        }
    }

    ull acc[4][5];                 // 4 k-pairs x 5 strided co
    #pragma unroll
    for (int kp = 0; kp < 4; kp++)
        #pragma unroll
        for (int j = 0; j < 5; j++) acc[kp][j] = 0ull;

    for (int sub = 0; sub < 4; sub++) {
        int bs0 = blockIdx.y * 128 + sub * 32;
        __syncthreads();
        // stage V: 1280 f4 coalesced (10 per thread)
        #pragma unroll
        for (int q = 0; q < 10; q++) {
            int idx = t + q*128;
            *(float4*)&sV[idx*4] =
                *(const float4*)(g_V + (size_t)bs0*CO + (size_t)idx*4);
        }
        __syncthreads();

        const float* xbase = &sXa[(sub*32)*32];
        #pragma unroll 2
        for (int b = 0; b < 32; b++) {
            const float* xr = xbase + b*32 + wk;
            ulonglong2 xa = *(const ulonglong2*)xr;        // k pairs 0,1
            ulonglong2 xc = *(const ulonglong2*)(xr + 4);  // k pairs 2,3
            ull xp[4] = {xa.x, xa.y, xc.x, xc.y};
            const float* vr = &sV[b*160 + l];
            ull vs[5];
            #pragma unroll
            for (int j = 0; j < 5; j++) vs[j] = splat2(vr[32*j]);
            #pragma unroll
            for (int kp = 0; kp < 4; kp++)
                #pragma unroll
                for (int j = 0; j < 5; j++)
                    acc[kp][j] = ffma2(xp[kp], vs[j], acc[kp][j]);
        }
    }
    __syncthreads();

    // spill partial G into sV region: sG[k][co], stride 162
    #pragma unroll
    for (int kp = 0; kp < 4; kp++) {
        float lo[5], hi[5];
        #pragma unroll
        for (int j = 0; j < 5; j++) unpack2(acc[kp][j], &lo[j], &hi[j]);
        float* ra = &sV[(wk + 2*kp)*162 + l];
        float* rb = ra + 162;
        #pragma unroll
        for (int j = 0; j < 5; j++) { ra[32*j] = lo[j]; rb[32*j] = hi[j]; }
    }
    __syncthreads();

    // contraction: warp w -> route r0+w
    int r = r0 + w;
    const float* G = &sV[(w*8)*162];
    for (int c = 0; c < CC; c++) {
        float4 w4 = *(const float4*)(W + ((size_t)r*CC + c)*OO*II + 4*l);
        int e0 = 4*l;
        float p = w4.x * G[((e0  )&7)*162 + c*16 + ((e0  )>>3)]
                + w4.y * G[((e0+1)&7)*162 + c*16 + ((e0+1)>>3)]
                + w4.z * G[((e0+2)&7)*162 + c*16 + ((e0+2)>>3)]
                + w4.w * G[((e0+3)&7)*162 + c*16 + ((e0+3)>>3)];
        #pragma unroll
        for (int off = 16; off; off >>= 1)
            p += __shfl_xor_sync(0xffffffffu, p, off);
        if (l == 0) atomicAdd(&g_b[c*RR + r], p * (1.0f / (float)BB));
    }
}

// ---------------------------------------------------------------------------
// softmax over routes per class ([c][r] layout)
// ---------------------------------------------------------------------------
__global__ void __launch_bounds__(256) k_softmax() {
    int c = blockIdx.x, t = threadIdx.x;
    __shared__ float red[8];

    float v[5];
    #pragma unroll
    for (int q = 0; q < 5; q++) {
        int r = t + q*256;
        v[q] = (r < RR) ? g_b[c*RR + r] : -1e30f;
    }
    float m = fmaxf(fmaxf(fmaxf(v[0], v[1]), fmaxf(v[2], v[3])), v[4]);
    #pragma unroll
    for (int off = 16; off; off >>= 1) m = fmaxf(m, __shfl_xor_sync(~0u, m, off));
    if ((t & 31) == 0) red[t >> 5] = m;
    __syncthreads();
    m = red[0];
    #pragma unroll
    for (int q = 1; q < 8; q++) m = fmaxf(m, red[q]);

    float e[5], sum = 0.0f;
    #pragma unroll
    for (int q = 0; q < 5; q++) {
        int r = t + q*256;
        e[q] = (r < RR) ? __expf(v[q] - m) : 0.0f;
        sum += e[q];
    }
    #pragma unroll
    for (int off = 16; off; off >>= 1) sum += __shfl_xor_sync(~0u, sum, off);
    __syncthreads();
    if ((t & 31) == 0) red[t >> 5] = sum;
    __syncthreads();
    sum = 0.0f;
    #pragma unroll
    for (int q = 0; q < 8; q++) sum += red[q];
    float inv = 1.0f / sum;

    #pragma unroll
    for (int q = 0; q < 5; q++) {
        int r = t + q*256;
        if (r < RR) g_c[c*RR + r] = e[q] * inv;
    }
}

// ---------------------------------------------------------------------------
extern "C" void kernel_launch(void* const* d_in, const int* in_sizes, int n_in,
                              void* d_out, int out_size) {
    const float* x = (const float*)d_in[0];
    const float* W = (const float*)d_in[1];
    if (in_sizes[0] == RR*CC*OO*II && in_sizes[1] == BB*RR*II) {
        W = (const float*)d_in[0];
        x = (const float*)d_in[1];
    }
    float* out = (float*)d_out;

    for (int it = 0; it < NITER; it++) {
        k_spart<<<dim3(KSPLIT, 4), 256>>>(x, W, it == 0 ? 1 : 0);
        k_sqreduce<<<160, 256>>>(out, it == NITER - 1 ? 1 : 0,
                                 it == 0 ? 1 : 0);
        if (it < NITER - 1) {
            k_agree<<<dim3(288, 2), 128>>>(x, W);
            k_softmax<<<CC, 256>>>();
        }
    }
}